// round 14
// baseline (speedup 1.0000x reference)
#include <cuda_runtime.h>

// LSTM B=4096, T=999, I=1, H=51, O=1, future=0.
//
// W=4 unlocked by halving register weights:
//   w1 (i|f rows) stays in 52 regs; w2 (g|o rows) lives in SMEM, TRANSPOSED
//   (w2sh[qp][rid]) so a q-OUTER loop loads each w2 pair once per step
//   (13 coalesced LDS.128/thread) and reuses it across all BT=7 batches.
//   Freed regs -> ~110 total -> 4 CTAs/SM at the 128-reg cap, NO spill
//   (R11 spilled at this occupancy with both weight sets in regs).
// BT=7, NTHR=128, grid=586 <= 592 slots: single wave, 16 warps/SM.
// x in a 64-step sliding window (2x64x8 floats, R7-style prefetch) since
// w2sh takes 21 KB. Everything else: R10 core (gate-pair threads, one
// barrier/step, batch-major h, tanh.approx, deferred FC lanes).

#define HID    51
#define KP     26
#define QP     13          // q-pairs (4 floats of K each)
#define SEQLEN 999
#define BT     7
#define XPAD   8
#define NTHR   128
#define BATCH  4096
#define GRID   586         // ceil(4096/7)

typedef unsigned long long u64;

__device__ __forceinline__ u64 pk2(float lo, float hi) {
    u64 r;
    asm("mov.b64 %0, {%1, %2};"
        : "=l"(r) : "r"(__float_as_uint(lo)), "r"(__float_as_uint(hi)));
    return r;
}
__device__ __forceinline__ void upk2(u64 v, float& lo, float& hi) {
    unsigned a, b;
    asm("mov.b64 {%0, %1}, %2;" : "=r"(a), "=r"(b) : "l"(v));
    lo = __uint_as_float(a); hi = __uint_as_float(b);
}
__device__ __forceinline__ u64 ffma2(u64 a, u64 b, u64 c) {
    u64 d; asm("fma.rn.f32x2 %0, %1, %2, %3;" : "=l"(d) : "l"(a), "l"(b), "l"(c));
    return d;
}
__device__ __forceinline__ u64 fmul2(u64 a, u64 b) {
    u64 d; asm("mul.rn.f32x2 %0, %1, %2;" : "=l"(d) : "l"(a), "l"(b));
    return d;
}
__device__ __forceinline__ float tanha(float x) {
    float r; asm("tanh.approx.f32 %0, %1;" : "=f"(r) : "f"(x));
    return r;
}

__global__ __launch_bounds__(NTHR, 4)
void lstm13_kernel(const float* __restrict__ input,   // (B, T, 1)
                   const float* __restrict__ W_ih,    // (4H, 1)
                   const float* __restrict__ W_hh,    // (4H, H)
                   const float* __restrict__ b_ih,    // (4H)
                   const float* __restrict__ b_hh,    // (4H)
                   const float* __restrict__ W_fc,    // (1, H)
                   const float* __restrict__ b_fc,    // (1)
                   float* __restrict__ out)           // (B, T, 1)
{
    __shared__ __align__(16) float xw[2][64][XPAD];       // 4 KB sliding x
    __shared__ __align__(16) u64   hsh[2][BT][KP];        // 2.9 KB
    __shared__ __align__(16) u64   w2sh[QP * 102 * 2];    // 21.2 KB transposed
    __shared__ __align__(16) u64   wfc2[KP];

    const int tid = threadIdx.x;
    const int b0  = blockIdx.x * BT;

    const int j = tid >> 1;           // unit 0..50 (active)
    const int p = tid & 1;            // 0 = (i,g), 1 = (f,o)+cell
    const bool active = (tid < 2 * HID);              // < 102
    const bool fcRole = (tid >= 104 && tid < 104 + BT);
    const int  fb     = tid - 104;
    const unsigned wmask = (tid >= 96) ? 0x3Fu : 0xFFFFFFFFu;

    const int row1 = p * HID + j;         // i or f
    const int row2 = (2 + p) * HID + j;   // g or o
    const int rid  = p * HID + j;         // w2sh row index 0..101

    // ---- one-time init ----
    for (int idx = tid; idx < 64 * XPAD; idx += NTHR) {   // x window 0
        int row = idx >> 3, col = idx & 7;
        float v = 0.0f;
        if (col < BT) {
            int bidx = min(b0 + col, BATCH - 1);
            v = input[bidx * SEQLEN + row];
        }
        xw[0][row][col] = v;
    }
    for (int idx = tid; idx < 2 * BT * KP; idx += NTHR)
        ((u64*)hsh)[idx] = 0ull;                          // h0 = 0
    if (tid < KP)
        wfc2[tid] = pk2(W_fc[2 * tid],
                        (2 * tid + 1 < HID) ? W_fc[2 * tid + 1] : 0.0f);
    if (active) {                                         // w2 -> smem (transposed)
        #pragma unroll
        for (int qp = 0; qp < QP; qp++) {
            const int k = 4 * qp;
            float e0 = W_hh[row2 * HID + k];
            float e1 = W_hh[row2 * HID + k + 1];
            float e2 = W_hh[row2 * HID + k + 2];
            float e3 = (k + 3 < HID) ? W_hh[row2 * HID + k + 3] : 0.0f;
            w2sh[(qp * 102 + rid) * 2]     = pk2(e0, e1);
            w2sh[(qp * 102 + rid) * 2 + 1] = pk2(e2, e3);
        }
    }

    u64 w1[KP];
    float bias1 = 0.f, bias2 = 0.f, wih1 = 0.f, wih2 = 0.f;
    if (active) {
        #pragma unroll
        for (int q = 0; q < KP; q++) {
            int k0 = 2 * q, k1 = 2 * q + 1;
            float a0 = W_hh[row1 * HID + k0];
            float a1 = (k1 < HID) ? W_hh[row1 * HID + k1] : 0.0f;
            w1[q] = pk2(a0, a1);
        }
        bias1 = b_ih[row1] + b_hh[row1];
        bias2 = b_ih[row2] + b_hh[row2];
        wih1  = W_ih[row1];
        wih2  = W_ih[row2];
    } else {
        #pragma unroll
        for (int q = 0; q < KP; q++) w1[q] = 0ull;
    }
    const float bfc = b_fc[0];

    // act = m2 * tanh(sc2 * a) + a2c  (row1 always sigmoid; row2: g->tanh,
    // o->sigmoid).  sigmoid(x) = 0.5*tanh(0.5x) + 0.5.
    const float sc2 = (p == 0) ? 1.0f : 0.5f;
    const float m2  = (p == 0) ? 1.0f : 0.5f;
    const float a2c = (p == 0) ? 0.0f : 0.5f;

    u64   cst0 = 0ull, cst1 = 0ull, cst2 = 0ull;   // batch pairs 01,23,45
    float cstS = 0.0f;                             // batch 6

    __syncthreads();

    #pragma unroll 1
    for (int t = 0; t < SEQLEN; t++) {
        const u64* __restrict__ hb = &hsh[t & 1][0][0];
        u64* __restrict__ hw = &hsh[(t + 1) & 1][0][0];
        const float* __restrict__ xrow = &xw[(t >> 6) & 1][t & 63][0];

        // ---- sliding-x prefetch (steps 0 mod 64; lands 64 steps later) ----
        if ((t & 63) == 0) {
            const int t0 = t + 64;
            if (t0 < SEQLEN) {
                const int buf = (t0 >> 6) & 1;
                for (int idx = tid; idx < 64 * XPAD; idx += NTHR) {
                    int row = idx >> 3, col = idx & 7;
                    int tt = t0 + row;
                    float v = 0.0f;
                    if (col < BT && tt < SEQLEN) {
                        int bidx = min(b0 + col, BATCH - 1);
                        v = input[bidx * SEQLEN + tt];
                    }
                    xw[buf][row][col] = v;
                }
            }
        }

        // ---- deferred FC for step t-1 (idle lanes; stable buffer) ----
        if (fcRole && t > 0) {
            const u64* __restrict__ hv = hb + fb * KP;
            u64 s0 = 0ull, s1 = 0ull;
            #pragma unroll
            for (int q = 0; q < KP; q += 2) {
                s0 = ffma2(hv[q],     wfc2[q],     s0);
                s1 = ffma2(hv[q + 1], wfc2[q + 1], s1);
            }
            float aa, ab, ac, ad;
            upk2(s0, aa, ab); upk2(s1, ac, ad);
            if (b0 + fb < BATCH)
                out[(b0 + fb) * SEQLEN + (t - 1)] = (aa + ab) + (ac + ad) + bfc;
        }

        if (active) {
            // ---- q-outer dots: w2 pair loaded ONCE, reused over 7 batches
            u64 a1[BT], a2[BT];
            #pragma unroll
            for (int b = 0; b < BT; b++) { a1[b] = 0ull; a2[b] = 0ull; }
            const ulonglong2* __restrict__ w2p =
                (const ulonglong2*)w2sh + rid;
            #pragma unroll
            for (int qp = 0; qp < QP; qp++) {
                const ulonglong2 wv = w2p[qp * 102];
                const u64 w1a = w1[2 * qp];
                const u64 w1b = w1[2 * qp + 1];
                #pragma unroll
                for (int b = 0; b < BT; b++) {
                    ulonglong2 hv = *(const ulonglong2*)(hb + b * KP + 2 * qp);
                    a1[b] = ffma2(w1a,  hv.x, a1[b]);
                    a1[b] = ffma2(w1b,  hv.y, a1[b]);
                    a2[b] = ffma2(wv.x, hv.x, a2[b]);
                    a2[b] = ffma2(wv.y, hv.y, a2[b]);
                }
            }
            asm volatile("" ::: "memory");

            // ---- tails: acts, exchange, cell/h update (pairs 01,23,45) ----
            auto tail2 = [&](int cb, u64 A0, u64 A1, u64 C0, u64 C1, u64& cc) {
                const float2 xv = make_float2(xrow[cb], xrow[cb + 1]);
                float lo, hi;
                upk2(A0, lo, hi); const float g10 = (lo + hi) + fmaf(xv.x, wih1, bias1);
                upk2(A1, lo, hi); const float g11 = (lo + hi) + fmaf(xv.y, wih1, bias1);
                upk2(C0, lo, hi); const float g20 = (lo + hi) + fmaf(xv.x, wih2, bias2);
                upk2(C1, lo, hi); const float g21 = (lo + hi) + fmaf(xv.y, wih2, bias2);
                const float s10 = fmaf(0.5f, tanha(0.5f * g10), 0.5f);
                const float s11 = fmaf(0.5f, tanha(0.5f * g11), 0.5f);
                const float s20 = fmaf(m2, tanha(sc2 * g20), a2c);
                const float s21 = fmaf(m2, tanha(sc2 * g21), a2c);
                u64 a1p = pk2(s10, s11);
                u64 a2p = pk2(s20, s21);
                u64 pr  = fmul2(a1p, a2p);             // p0: sig(i)*tanh(g)
                u64 rr  = __shfl_xor_sync(wmask, pr, 1, 32);
                if (p == 1) {
                    cc = ffma2(a1p, cc, rr);           // c = sig(f)*c + i*g
                    float c0f, c1f; upk2(cc, c0f, c1f);
                    const float h0v = s20 * tanha(c0f);
                    const float h1v = s21 * tanha(c1f);
                    const int jh = j >> 1, jl = j & 1;
                    ((float*)(hw + cb * KP + jh))[jl]       = h0v;
                    ((float*)(hw + (cb + 1) * KP + jh))[jl] = h1v;
                }
            };

            tail2(0, a1[0], a1[1], a2[0], a2[1], cst0);
            tail2(2, a1[2], a1[3], a2[2], a2[3], cst1);
            tail2(4, a1[4], a1[5], a2[4], a2[5], cst2);

            // ---- tail: single batch 6 (scalar path) ----
            {
                const float xv = xrow[6];
                float lo, hi;
                upk2(a1[6], lo, hi); const float g1 = (lo + hi) + fmaf(xv, wih1, bias1);
                upk2(a2[6], lo, hi); const float g2 = (lo + hi) + fmaf(xv, wih2, bias2);
                const float s1 = fmaf(0.5f, tanha(0.5f * g1), 0.5f);
                const float s2 = fmaf(m2, tanha(sc2 * g2), a2c);
                const float pr = s1 * s2;              // p0: sig(i)*tanh(g)
                const float rr = __shfl_xor_sync(wmask, pr, 1, 32);
                if (p == 1) {
                    cstS = fmaf(s1, cstS, rr);
                    const float hv6 = s2 * tanha(cstS);
                    const int jh = j >> 1, jl = j & 1;
                    ((float*)(hw + 6 * KP + jh))[jl] = hv6;
                }
            }
        }
        __syncthreads();
    }

    // final FC for t = SEQLEN-1
    if (fcRole && b0 + fb < BATCH) {
        const u64* __restrict__ hv = &hsh[SEQLEN & 1][fb][0];
        u64 s0 = 0ull, s1 = 0ull;
        #pragma unroll
        for (int q = 0; q < KP; q += 2) {
            s0 = ffma2(hv[q],     wfc2[q],     s0);
            s1 = ffma2(hv[q + 1], wfc2[q + 1], s1);
        }
        float aa, ab, ac, ad;
        upk2(s0, aa, ab); upk2(s1, ac, ad);
        out[(b0 + fb) * SEQLEN + (SEQLEN - 1)] = (aa + ab) + (ac + ad) + bfc;
    }
}

extern "C" void kernel_launch(void* const* d_in, const int* in_sizes, int n_in,
                              void* d_out, int out_size) {
    const float* input = (const float*)d_in[0];
    const float* W_ih  = (const float*)d_in[1];
    const float* W_hh  = (const float*)d_in[2];
    const float* b_ih  = (const float*)d_in[3];
    const float* b_hh  = (const float*)d_in[4];
    const float* W_fc  = (const float*)d_in[5];
    const float* b_fc  = (const float*)d_in[6];
    // d_in[7] = future (0) — ignored.
    float* out = (float*)d_out;

    lstm13_kernel<<<GRID, NTHR>>>(input, W_ih, W_hh, b_ih, b_hh,
                                  W_fc, b_fc, out);
}